// round 9
// baseline (speedup 1.0000x reference)
#include <cuda_runtime.h>
#include <cstdint>

#define B_N 32768
#define D_N 1024
#define S_N 64
#define O_N 4
#define SPW 4            // samples per warp in gemm
#define WPB 8            // warps per gemm block
#define SPB (SPW * WPB)  // 32 samples per gemm block
#define NBLK 128         // hist/scatter blocks (256 threads each)
#define TBLK 64          // transpose blocks appended to hist grid
#define STAGE_F4 1024    // float4 per x stage (32 samples * 32 float4)
#define W_F4 1024        // float4 per W tile (O_N * D_N / 4)

__device__ int    g_bh[NBLK][S_N];    // per-block histogram
__device__ int    g_base[NBLK][S_N];  // per-block scatter base
__device__ int    g_perm[B_N];
__device__ float4 g_Wt[S_N * W_F4];   // W transposed to [S][O][D] (1 MB scratch)

// ---------------------------------------------------------------- cp.async helpers
__device__ __forceinline__ void cp16(uint32_t dst_smem, const void* src) {
    asm volatile("cp.async.cg.shared.global [%0], [%1], 16;" :: "r"(dst_smem), "l"(src));
}
__device__ __forceinline__ void cp_commit() {
    asm volatile("cp.async.commit_group;" ::: "memory");
}
__device__ __forceinline__ void cp_wait1() {
    asm volatile("cp.async.wait_group 1;" ::: "memory");
}

// ---------------------------------------------------------------- hist + W transpose (fused, disjoint blocks)
__global__ void k_pre(const int* __restrict__ sid, const float4* __restrict__ W4) {
    if (blockIdx.x < NBLK) {
        __shared__ int h[S_N];
        int t = threadIdx.x;
        if (t < S_N) h[t] = 0;
        __syncthreads();
        int i = blockIdx.x * 256 + t;
        atomicAdd(&h[sid[i]], 1);
        __syncthreads();
        if (t < S_N) g_bh[blockIdx.x][t] = h[t];
    } else {
        // transpose: W[s][d][o] (float4 per d) -> Wt[s][o][d]
        float* Wt = reinterpret_cast<float*>(g_Wt);
        int b = blockIdx.x - NBLK;
#pragma unroll
        for (int j = 0; j < 4; ++j) {
            int t = b * 1024 + j * 256 + threadIdx.x;   // 0..65535 = S*D
            int s = t >> 10;
            int d = t & 1023;
            float4 w = W4[t];
            Wt[(s * 4 + 0) * D_N + d] = w.x;
            Wt[(s * 4 + 1) * D_N + d] = w.y;
            Wt[(s * 4 + 2) * D_N + d] = w.z;
            Wt[(s * 4 + 3) * D_N + d] = w.w;
        }
    }
}

// ---------------------------------------------------------------- scan: subject offsets + per-block bases
__global__ void k_scan() {
    __shared__ int cnt[S_N];
    __shared__ int off[S_N];
    int s = threadIdx.x;           // 64 threads
    int c = 0;
#pragma unroll 8
    for (int b = 0; b < NBLK; ++b) c += g_bh[b][s];
    cnt[s] = c;
    __syncthreads();
    if (s == 0) {
        int a = 0;
        for (int j = 0; j < S_N; ++j) { off[j] = a; a += cnt[j]; }
    }
    __syncthreads();
    int run = off[s];
    for (int b = 0; b < NBLK; ++b) {
        g_base[b][s] = run;
        run += g_bh[b][s];
    }
}

// ---------------------------------------------------------------- scatter
__global__ void k_scatter(const int* __restrict__ sid) {
    __shared__ int h[S_N];
    int t = threadIdx.x;
    if (t < S_N) h[t] = 0;
    __syncthreads();
    int i = blockIdx.x * blockDim.x + t;
    int s = sid[i];
    int r = atomicAdd(&h[s], 1);
    g_perm[g_base[blockIdx.x][s] + r] = i;
}

// ---------------------------------------------------------------- gemm: cp.async double-buffered x, smem W
__global__ void __launch_bounds__(256) k_gemm(
    const float* __restrict__ x,
    const int*   __restrict__ sid,
    const float* __restrict__ bias,
    float*       __restrict__ out)
{
    __shared__ float4 sW[W_F4];              // 16 KB: one subject's transposed W
    __shared__ float4 sX[2 * STAGE_F4];      // 32 KB: 2-stage x pipeline

    int tid  = threadIdx.x;
    int warp = tid >> 5;
    int lane = tid & 31;
    int blockBase = blockIdx.x * SPB;

    // block uniformity: samples sorted by subject -> first==last => all equal
    int sFirst = sid[g_perm[blockBase]];
    int sLast  = sid[g_perm[blockBase + SPB - 1]];
    bool uni = (sFirst == sLast);

    // ---- x prefetch mapping: 8 threads per sample, 4 x 16B each per stage
    int cidx = g_perm[blockBase + (tid >> 3)];
    const float4* csrc = reinterpret_cast<const float4*>(x)
                         + cidx * (D_N / 4) + (tid & 7) * 4;
    uint32_t sx_base = (uint32_t)__cvta_generic_to_shared(sX)
                       + (uint32_t)(((tid >> 3) * 32 + (tid & 7) * 4) * 16);

    // ---- prologue: group0 = W (if uniform) + stage0 ; group1 = stage1
    if (uni) {
        const float4* wsrc = g_Wt + sFirst * W_F4;
        uint32_t wdst = (uint32_t)__cvta_generic_to_shared(sW) + tid * 16u;
#pragma unroll
        for (int j = 0; j < 4; ++j)
            cp16(wdst + j * 4096u, wsrc + j * 256 + tid);
    }
#pragma unroll
    for (int j = 0; j < 4; ++j)
        cp16(sx_base + j * 16u, csrc + j);               // stage 0 (k=0)
    cp_commit();
#pragma unroll
    for (int j = 0; j < 4; ++j)
        cp16(sx_base + 16384u + j * 16u, csrc + 32 + j); // stage 1 (k=1)
    cp_commit();

    // ---- per-warp sample bookkeeping
    int idx[SPW], sd[SPW];
#pragma unroll
    for (int s = 0; s < SPW; ++s) {
        idx[s] = g_perm[blockBase + warp * SPW + s];
        sd[s]  = sid[idx[s]];
    }

    float acc[SPW][O_N];
#pragma unroll
    for (int s = 0; s < SPW; ++s)
#pragma unroll
        for (int o = 0; o < O_N; ++o) acc[s][o] = 0.0f;

    // ---- mainloop: 8 k-steps of 512B per sample
    for (int k = 0; k < 8; ++k) {
        cp_wait1();                // stage k complete (and W at k=0)
        __syncthreads();

        const float4* st = sX + (k & 1) * STAGE_F4;

        if (uni) {
            float4 xv[SPW];
#pragma unroll
            for (int s = 0; s < SPW; ++s)
                xv[s] = st[(warp * SPW + s) * 32 + lane];
            int dv = k * 32 + lane;
            float4 w0 = sW[0 * 256 + dv];
            float4 w1 = sW[1 * 256 + dv];
            float4 w2 = sW[2 * 256 + dv];
            float4 w3 = sW[3 * 256 + dv];
#pragma unroll
            for (int s = 0; s < SPW; ++s) {
                acc[s][0] += xv[s].x * w0.x + xv[s].y * w0.y + xv[s].z * w0.z + xv[s].w * w0.w;
                acc[s][1] += xv[s].x * w1.x + xv[s].y * w1.y + xv[s].z * w1.z + xv[s].w * w1.w;
                acc[s][2] += xv[s].x * w2.x + xv[s].y * w2.y + xv[s].z * w2.z + xv[s].w * w2.w;
                acc[s][3] += xv[s].x * w3.x + xv[s].y * w3.y + xv[s].z * w3.z + xv[s].w * w3.w;
            }
        } else {
            // boundary block (<=63 of 1024): per-sample W from global, x from smem
            int dv = k * 32 + lane;
#pragma unroll
            for (int s = 0; s < SPW; ++s) {
                const float4* Wt4 = g_Wt + sd[s] * W_F4;
                float4 xv = st[(warp * SPW + s) * 32 + lane];
                float4 w0 = Wt4[0 * 256 + dv];
                float4 w1 = Wt4[1 * 256 + dv];
                float4 w2 = Wt4[2 * 256 + dv];
                float4 w3 = Wt4[3 * 256 + dv];
                acc[s][0] += xv.x * w0.x + xv.y * w0.y + xv.z * w0.z + xv.w * w0.w;
                acc[s][1] += xv.x * w1.x + xv.y * w1.y + xv.z * w1.z + xv.w * w1.w;
                acc[s][2] += xv.x * w2.x + xv.y * w2.y + xv.z * w2.z + xv.w * w2.w;
                acc[s][3] += xv.x * w3.x + xv.y * w3.y + xv.z * w3.z + xv.w * w3.w;
            }
        }

        __syncthreads();           // all warps done with slot (k&1) before refill
        if (k + 2 < 8) {
            int kn = k + 2;
            uint32_t dst = sx_base + (uint32_t)((kn & 1) * 16384);
#pragma unroll
            for (int j = 0; j < 4; ++j)
                cp16(dst + j * 16u, csrc + kn * 32 + j);
        }
        cp_commit();               // commit (possibly empty) to keep group count in sync
    }

    // ---- warp butterfly reduction
#pragma unroll
    for (int s = 0; s < SPW; ++s)
#pragma unroll
        for (int o = 0; o < O_N; ++o) {
#pragma unroll
            for (int off = 16; off; off >>= 1)
                acc[s][o] += __shfl_xor_sync(0xffffffffu, acc[s][o], off);
        }

    // ---- lane s writes sample s
    if (lane < SPW) {
        int s = lane;
        float4 bb = reinterpret_cast<const float4*>(bias)[sd[s]];
        float4 r;
        r.x = acc[s][0] + bb.x;
        r.y = acc[s][1] + bb.y;
        r.z = acc[s][2] + bb.z;
        r.w = acc[s][3] + bb.w;
        reinterpret_cast<float4*>(out)[idx[s]] = r;
    }
}

// ---------------------------------------------------------------- launch
extern "C" void kernel_launch(void* const* d_in, const int* in_sizes, int n_in,
                              void* d_out, int out_size) {
    const float* x    = (const float*)d_in[0];   // [B, D]
    const int*   sid  = (const int*)d_in[1];     // [B]
    const float* W    = (const float*)d_in[2];   // [S, D, O]
    const float* bias = (const float*)d_in[3];   // [S, O]
    float*       out  = (float*)d_out;           // [B, O]

    (void)in_sizes; (void)n_in; (void)out_size;

    k_pre<<<NBLK + TBLK, 256>>>(sid, (const float4*)W);
    k_scan<<<1, 64>>>();
    k_scatter<<<NBLK, 256>>>(sid);
    k_gemm<<<B_N / SPB, 256>>>(x, sid, bias, out);
}

// round 10
// speedup vs baseline: 1.1871x; 1.1871x over previous
#include <cuda_runtime.h>

#define B_N 32768
#define D_N 1024
#define S_N 64
#define O_N 4
#define SPW 2            // samples per warp in gemm
#define WPB 8            // warps per gemm block
#define SPB (SPW * WPB)  // 16 samples per gemm block
#define NBLK 128         // hist/scatter blocks (256 threads each)
#define TBLK 64          // transpose blocks appended to hist grid
#define W_F4 1024        // float4 per W tile (O_N * D_N / 4)

__device__ int    g_bh[NBLK][S_N];    // per-block histogram
__device__ int    g_base[NBLK][S_N];  // per-block scatter base
__device__ int    g_perm[B_N];
__device__ float4 g_Wt[S_N * W_F4];   // W transposed to [S][O][D] (1 MB scratch)

// ---------------------------------------------------------------- hist + W transpose (fused, disjoint blocks)
__global__ void k_pre(const int* __restrict__ sid, const float4* __restrict__ W4) {
    if (blockIdx.x < NBLK) {
        __shared__ int h[S_N];
        int t = threadIdx.x;
        if (t < S_N) h[t] = 0;
        __syncthreads();
        int i = blockIdx.x * 256 + t;
        atomicAdd(&h[sid[i]], 1);
        __syncthreads();
        if (t < S_N) g_bh[blockIdx.x][t] = h[t];
    } else {
        // transpose: W[s][d][o] (float4 per d) -> Wt[s][o][d]
        float* Wt = reinterpret_cast<float*>(g_Wt);
        int b = blockIdx.x - NBLK;
#pragma unroll
        for (int j = 0; j < 4; ++j) {
            int t = b * 1024 + j * 256 + threadIdx.x;   // 0..65535 = S*D
            int s = t >> 10;
            int d = t & 1023;
            float4 w = W4[t];
            Wt[(s * 4 + 0) * D_N + d] = w.x;
            Wt[(s * 4 + 1) * D_N + d] = w.y;
            Wt[(s * 4 + 2) * D_N + d] = w.z;
            Wt[(s * 4 + 3) * D_N + d] = w.w;
        }
    }
}

// ---------------------------------------------------------------- scan: subject offsets + per-block bases
__global__ void k_scan() {
    __shared__ int cnt[S_N];
    __shared__ int off[S_N];
    int s = threadIdx.x;           // 64 threads
    int c = 0;
#pragma unroll 8
    for (int b = 0; b < NBLK; ++b) c += g_bh[b][s];
    cnt[s] = c;
    __syncthreads();
    if (s == 0) {
        int a = 0;
        for (int j = 0; j < S_N; ++j) { off[j] = a; a += cnt[j]; }
    }
    __syncthreads();
    int run = off[s];
    for (int b = 0; b < NBLK; ++b) {
        g_base[b][s] = run;
        run += g_bh[b][s];
    }
}

// ---------------------------------------------------------------- scatter
__global__ void k_scatter(const int* __restrict__ sid) {
    __shared__ int h[S_N];
    int t = threadIdx.x;
    if (t < S_N) h[t] = 0;
    __syncthreads();
    int i = blockIdx.x * blockDim.x + t;
    int s = sid[i];
    int r = atomicAdd(&h[s], 1);
    g_perm[g_base[blockIdx.x][s] + r] = i;
}

// ---------------------------------------------------------------- gemm: full x preload (16 LDG.128/warp), smem W
__global__ void __launch_bounds__(256) k_gemm(
    const float* __restrict__ x,
    const int*   __restrict__ sid,
    const float* __restrict__ bias,
    float*       __restrict__ out)
{
    __shared__ float4 sW[W_F4];    // 16 KB: one subject's transposed W [O][D/4]

    int tid  = threadIdx.x;
    int warp = tid >> 5;
    int lane = tid & 31;
    int blockBase = blockIdx.x * SPB;

    // block uniformity: samples sorted by subject -> first==last => all equal
    int sFirst = sid[g_perm[blockBase]];
    int sLast  = sid[g_perm[blockBase + SPB - 1]];
    bool uni = (sFirst == sLast);

    int idx[SPW], sd[SPW];
#pragma unroll
    for (int s = 0; s < SPW; ++s) {
        idx[s] = g_perm[blockBase + warp * SPW + s];
        sd[s]  = sid[idx[s]];
    }

    const float4* x4 = reinterpret_cast<const float4*>(x);

    // ---- front-batched x preload: 16 independent LDG.128 = 8 KB in flight per warp
    float4 xv[SPW][8];
#pragma unroll
    for (int s = 0; s < SPW; ++s) {
        const float4* xp = x4 + idx[s] * (D_N / 4) + lane;
#pragma unroll
        for (int k = 0; k < 8; ++k)
            xv[s][k] = xp[k * 32];
    }

    // ---- cooperative W tile load (overlaps with x-load latency)
    if (uni) {
        const float4* wsrc = g_Wt + sFirst * W_F4;
#pragma unroll
        for (int j = 0; j < 4; ++j)
            sW[j * 256 + tid] = wsrc[j * 256 + tid];
    }
    __syncthreads();

    float acc[SPW][O_N];
#pragma unroll
    for (int s = 0; s < SPW; ++s)
#pragma unroll
        for (int o = 0; o < O_N; ++o) acc[s][o] = 0.0f;

    if (uni) {
#pragma unroll
        for (int k = 0; k < 8; ++k) {
            int dv = k * 32 + lane;
            float4 w0 = sW[0 * 256 + dv];
            float4 w1 = sW[1 * 256 + dv];
            float4 w2 = sW[2 * 256 + dv];
            float4 w3 = sW[3 * 256 + dv];
#pragma unroll
            for (int s = 0; s < SPW; ++s) {
                float4 v = xv[s][k];
                acc[s][0] += v.x * w0.x + v.y * w0.y + v.z * w0.z + v.w * w0.w;
                acc[s][1] += v.x * w1.x + v.y * w1.y + v.z * w1.z + v.w * w1.w;
                acc[s][2] += v.x * w2.x + v.y * w2.y + v.z * w2.z + v.w * w2.w;
                acc[s][3] += v.x * w3.x + v.y * w3.y + v.z * w3.z + v.w * w3.w;
            }
        }
    } else {
        // boundary block (<=63 of 2048): per-sample W from global (L2-resident)
#pragma unroll
        for (int s = 0; s < SPW; ++s) {
            const float4* Wt4 = g_Wt + sd[s] * W_F4;
#pragma unroll
            for (int k = 0; k < 8; ++k) {
                int dv = k * 32 + lane;
                float4 v  = xv[s][k];
                float4 w0 = Wt4[0 * 256 + dv];
                float4 w1 = Wt4[1 * 256 + dv];
                float4 w2 = Wt4[2 * 256 + dv];
                float4 w3 = Wt4[3 * 256 + dv];
                acc[s][0] += v.x * w0.x + v.y * w0.y + v.z * w0.z + v.w * w0.w;
                acc[s][1] += v.x * w1.x + v.y * w1.y + v.z * w1.z + v.w * w1.w;
                acc[s][2] += v.x * w2.x + v.y * w2.y + v.z * w2.z + v.w * w2.w;
                acc[s][3] += v.x * w3.x + v.y * w3.y + v.z * w3.z + v.w * w3.w;
            }
        }
    }

    // ---- warp butterfly reduction
#pragma unroll
    for (int s = 0; s < SPW; ++s)
#pragma unroll
        for (int o = 0; o < O_N; ++o) {
#pragma unroll
            for (int off = 16; off; off >>= 1)
                acc[s][o] += __shfl_xor_sync(0xffffffffu, acc[s][o], off);
        }

    // ---- lane s writes sample s
    if (lane < SPW) {
        int s = lane;
        float4 bb = reinterpret_cast<const float4*>(bias)[sd[s]];
        float4 r;
        r.x = acc[s][0] + bb.x;
        r.y = acc[s][1] + bb.y;
        r.z = acc[s][2] + bb.z;
        r.w = acc[s][3] + bb.w;
        reinterpret_cast<float4*>(out)[idx[s]] = r;
    }
}

// ---------------------------------------------------------------- launch
extern "C" void kernel_launch(void* const* d_in, const int* in_sizes, int n_in,
                              void* d_out, int out_size) {
    const float* x    = (const float*)d_in[0];   // [B, D]
    const int*   sid  = (const int*)d_in[1];     // [B]
    const float* W    = (const float*)d_in[2];   // [S, D, O]
    const float* bias = (const float*)d_in[3];   // [S, O]
    float*       out  = (float*)d_out;           // [B, O]

    (void)in_sizes; (void)n_in; (void)out_size;

    k_pre<<<NBLK + TBLK, 256>>>(sid, (const float4*)W);
    k_scan<<<1, 64>>>();
    k_scatter<<<NBLK, 256>>>(sid);
    k_gemm<<<B_N / SPB, 256>>>(x, sid, bias, out);
}